// round 13
// baseline (speedup 1.0000x reference)
#include <cuda_runtime.h>
#include <math.h>

#define NPOS 32768      // 32^3 fine positions
#define NCELL 4096      // 16^3 coarse cells
#define CIN 64
#define COFF 81         // 3 * 27 offset channels
#define COUT 32
#define CCHUNK 16
#define OPAD 84         // 3 sections x 28 (27 padded for f32x2 pairs)

// Scratch (no allocs allowed -> __device__ globals)
__device__ float g_off[COFF * NPOS];            // offset conv output, [ch][pos]
__device__ float g_weff[8 * CIN * 8 * OPAD];    // [par][c][j][osec*28+oo]
__device__ float g_wT[27 * CIN * COUT];         // main weights [tap][c][oc]
__device__ float g_scale[COUT];
__device__ float g_shift[COUT];

// ---- packed f32x2 helpers -------------------------------------------------
__device__ __forceinline__ unsigned long long pack2(float v) {
    unsigned long long r;
    unsigned u = __float_as_uint(v);
    asm("mov.b64 %0, {%1, %1};" : "=l"(r) : "r"(u));
    return r;
}
__device__ __forceinline__ void fma2(unsigned long long& d,
                                     unsigned long long a,
                                     unsigned long long b) {
    asm("fma.rn.f32x2 %0, %1, %2, %0;" : "+l"(d) : "l"(a), "l"(b));
}
__device__ __forceinline__ float lo2(unsigned long long v) {
    return __uint_as_float((unsigned)(v & 0xffffffffULL));
}
__device__ __forceinline__ float hi2(unsigned long long v) {
    return __uint_as_float((unsigned)(v >> 32));
}

// ---------------------------------------------------------------------------
// K0: transpose main conv weights to [tap][c][oc] (one-time, tiny).
// ---------------------------------------------------------------------------
__global__ void k_wT(const float* __restrict__ wmain) {
    int t = blockIdx.x * blockDim.x + threadIdx.x;
    if (t >= 27 * CIN * COUT) return;
    int oc  = t & 31;
    int c   = (t >> 5) & 63;
    int tap = t >> 11;
    g_wT[t] = wmain[(oc * CIN + c) * 27 + tap];
}

// ---------------------------------------------------------------------------
// K1: parity-combined effective weights, [par][c][j][osec*28+oo] padded.
// ---------------------------------------------------------------------------
__global__ void k_weff(const float* __restrict__ w_off) {
    int t = blockIdx.x * blockDim.x + threadIdx.x;
    if (t >= 8 * CIN * 8 * OPAD) return;
    int o84  = t % OPAD;
    int j    = (t / OPAD) & 7;
    int c    = (t / (OPAD * 8)) & 63;
    int par  = t / (OPAD * 8 * CIN);
    int osec = o84 / 28, oo = o84 % 28;
    if (oo >= 27) { g_weff[t] = 0.f; return; }
    int o = osec * 27 + oo;
    int pd = (par >> 2) & 1, ph = (par >> 1) & 1, pw = par & 1;
    int jd = (j >> 2) & 1,  jh = (j >> 1) & 1,  jw = j & 1;
    int sd = jd * (1 + pd), nd = (pd != jd) ? 2 : 1;
    int sh = jh * (1 + ph), nh = (ph != jh) ? 2 : 1;
    int sw = jw * (1 + pw), nw = (pw != jw) ? 2 : 1;
    const float* wb = w_off + (o * CIN + c) * 27;
    float s = 0.f;
    for (int a = 0; a < nd; a++)
        for (int bq = 0; bq < nh; bq++)
            for (int cc = 0; cc < nw; cc++)
                s += wb[(sd + a) * 9 + (sh + bq) * 3 + (sw + cc)];
    g_weff[t] = s;
}

// ---------------------------------------------------------------------------
// K2: offset conv (R12 version, measured good): 2-position blocking +
// 3-way osec split + f32x2. grid = 384, 128 thr.
// ---------------------------------------------------------------------------
__global__ void __launch_bounds__(128) k_offconv(const float* __restrict__ x,
                                                 const float* __restrict__ b_off) {
    __shared__ __align__(16) float sw[CCHUNK * 8 * 28];   // 14.3 KB
    int bid  = blockIdx.x;
    int par  = bid / 48;
    int rest = bid % 48;
    int tile = rest / 3;
    int osec = rest % 3;
    int ti   = threadIdx.x;
    int q0 = tile * 256 + ti;                 // and q0 + 128
    int pd = (par >> 2) & 1, ph = (par >> 1) & 1, pw = par & 1;

    int sp[2][8]; float msk[2][8];
    #pragma unroll
    for (int s = 0; s < 2; s++) {
        int q = q0 + s * 128;
        int qw = q & 15, qh = (q >> 4) & 15, qd = q >> 8;
        #pragma unroll
        for (int j = 0; j < 8; j++) {
            int cd = qd + pd - 1 + ((j >> 2) & 1);
            int ch = qh + ph - 1 + ((j >> 1) & 1);
            int cw = qw + pw - 1 + (j & 1);
            bool v = (unsigned)cd < 16u && (unsigned)ch < 16u && (unsigned)cw < 16u;
            sp[s][j]  = v ? ((cd * 16 + ch) * 16 + cw) : 0;
            msk[s][j] = v ? 1.f : 0.f;
        }
    }

    unsigned long long acc[2][14];
    #pragma unroll
    for (int s = 0; s < 2; s++)
        #pragma unroll
        for (int i = 0; i < 14; i++) acc[s][i] = 0ULL;

    #pragma unroll 1
    for (int c0 = 0; c0 < CIN; c0 += CCHUNK) {
        __syncthreads();
        for (int i = ti; i < CCHUNK * 8 * 28; i += 128) {
            int cc = i / (8 * 28);
            int ii = i % (8 * 28);
            int j  = ii / 28, oo = ii % 28;
            sw[i] = g_weff[(((size_t)(par * CIN + c0 + cc)) * 8 + j) * OPAD + osec * 28 + oo];
        }
        __syncthreads();
        #pragma unroll 1
        for (int cc = 0; cc < CCHUNK; cc++) {
            const float* xb = x + (c0 + cc) * NCELL;
            float xv[2][8];
            #pragma unroll
            for (int s = 0; s < 2; s++)
                #pragma unroll
                for (int j = 0; j < 8; j++)
                    xv[s][j] = msk[s][j] * __ldg(&xb[sp[s][j]]);
            #pragma unroll
            for (int j = 0; j < 8; j++) {
                unsigned long long x0 = pack2(xv[0][j]);
                unsigned long long x1 = pack2(xv[1][j]);
                const ulonglong2* wr = (const ulonglong2*)(sw + (cc * 8 + j) * 28);
                #pragma unroll
                for (int op = 0; op < 7; op++) {
                    ulonglong2 wp = wr[op];
                    fma2(acc[0][2*op],   x0, wp.x);
                    fma2(acc[0][2*op+1], x0, wp.y);
                    fma2(acc[1][2*op],   x1, wp.x);
                    fma2(acc[1][2*op+1], x1, wp.y);
                }
            }
        }
    }
    #pragma unroll
    for (int s = 0; s < 2; s++) {
        int q = q0 + s * 128;
        int qw = q & 15, qh = (q >> 4) & 15, qd = q >> 8;
        int df = 2*qd + pd, hf = 2*qh + ph, wf = 2*qw + pw;
        int p = (df * 32 + hf) * 32 + wf;
        #pragma unroll
        for (int i = 0; i < 14; i++) {
            int o0 = 2 * i, o1 = 2 * i + 1;
            g_off[(osec * 27 + o0) * NPOS + p] = lo2(acc[s][i]) + b_off[osec * 27 + o0];
            if (o1 < 27)
                g_off[(osec * 27 + o1) * NPOS + p] = hi2(acc[s][i]) + b_off[osec * 27 + o1];
        }
    }
}

// ---------------------------------------------------------------------------
// K3: deformable conv, occupancy-optimized. Block = 32 positions x 4
// channel-quarters x 2 oc-halves (256 thr); thread: 1 pos, 16 ch, 16 oc.
// Small register footprint -> 3 blocks/SM (24 warps) to hide L2 gather
// latency. Warp = 32 consecutive positions (coalesced gathers).
// ---------------------------------------------------------------------------
__global__ void __launch_bounds__(256, 3) k_deform(const float* __restrict__ x,
                                                   const float* __restrict__ bmain,
                                                   float* __restrict__ out) {
    __shared__ __align__(16) float ws[CIN * COUT];  // per-tap weights [c][oc], 8 KB
    __shared__ float red[2 * 64 * 17];              // cq-reduction, padded
    int tid  = threadIdx.x;
    int posi = tid & 31;
    int cq   = (tid >> 5) & 3;                // channel quarter
    int og   = tid >> 7;                      // oc half
    int g    = posi + (og << 5);              // reduction group 0..63
    int p = blockIdx.x * 32 + posi;
    int wf = p & 31, hf = (p >> 5) & 31, df = p >> 10;

    unsigned long long acc2[8];
    #pragma unroll
    for (int i = 0; i < 8; i++) acc2[i] = 0ULL;

    const float* xbase = x + cq * 16 * NCELL;

    #pragma unroll 1
    for (int tap = 0; tap < 27; tap++) {
        __syncthreads();
        {   // coalesced 8KB copy
            const float4* src = (const float4*)(g_wT + tap * CIN * COUT);
            float4* dst = (float4*)ws;
            #pragma unroll
            for (int i = 0; i < 2; i++) dst[tid + i * 256] = src[tid + i * 256];
        }
        __syncthreads();

        int kd = tap / 9, kh = (tap / 3) % 3, kw = tap % 3;
        float pdc = (float)(df + kd - 1) + __ldg(&g_off[(tap * 3 + 0) * NPOS + p]);
        float phc = (float)(hf + kh - 1) + __ldg(&g_off[(tap * 3 + 1) * NPOS + p]);
        float pwc = (float)(wf + kw - 1) + __ldg(&g_off[(tap * 3 + 2) * NPOS + p]);
        float fd0 = floorf(pdc), fh0 = floorf(phc), fw0 = floorf(pwc);
        int id0 = (int)fd0, ih0 = (int)fh0, iw0 = (int)fw0;
        float fd = pdc - fd0, fh = phc - fh0, fw = pwc - fw0;

        int cD[2], cH[2], cW[2]; float wD[2], wH[2], wW[2];
        cD[0] = id0 >> 1; cD[1] = (id0 + 1) >> 1;
        cH[0] = ih0 >> 1; cH[1] = (ih0 + 1) >> 1;
        cW[0] = iw0 >> 1; cW[1] = (iw0 + 1) >> 1;
        bool ed = !(id0 & 1), eh = !(ih0 & 1), ew = !(iw0 & 1);
        wD[0] = ed ? 1.f : 1.f - fd;  wD[1] = ed ? 0.f : fd;
        wH[0] = eh ? 1.f : 1.f - fh;  wH[1] = eh ? 0.f : fh;
        wW[0] = ew ? 1.f : 1.f - fw;  wW[1] = ew ? 0.f : fw;
        if ((unsigned)cD[0] >= 16u) wD[0] = 0.f;
        if ((unsigned)cD[1] >= 16u) wD[1] = 0.f;
        if ((unsigned)cH[0] >= 16u) wH[0] = 0.f;
        if ((unsigned)cH[1] >= 16u) wH[1] = 0.f;
        if ((unsigned)cW[0] >= 16u) wW[0] = 0.f;
        if ((unsigned)cW[1] >= 16u) wW[1] = 0.f;

        float samp[16];
        #pragma unroll
        for (int i = 0; i < 16; i++) samp[i] = 0.f;

        #pragma unroll
        for (int jd = 0; jd < 2; jd++)
        #pragma unroll
        for (int jh = 0; jh < 2; jh++)
        #pragma unroll
        for (int jw = 0; jw < 2; jw++) {
            float wj = wD[jd] * wH[jh] * wW[jw];
            if (wj != 0.f) {
                const float* xb = xbase + ((cD[jd] * 16 + cH[jh]) * 16 + cW[jw]);
                #pragma unroll
                for (int cc = 0; cc < 16; cc++)
                    samp[cc] += wj * __ldg(xb + cc * NCELL);
            }
        }

        // contraction: acc2[8 pairs] += samp[cc] * W[cq*16+cc][og*16..+15]
        #pragma unroll
        for (int cc = 0; cc < 16; cc++) {
            unsigned long long v = pack2(samp[cc]);
            const ulonglong2* wrow =
                (const ulonglong2*)(ws + (cq * 16 + cc) * 32 + og * 16);
            #pragma unroll
            for (int k = 0; k < 4; k++) {
                ulonglong2 wp = wrow[k];
                fma2(acc2[2*k],   v, wp.x);
                fma2(acc2[2*k+1], v, wp.y);
            }
        }
    }

    // unpack, then reduce over the 4 channel quarters per (posi, og)
    float acc[16];
    #pragma unroll
    for (int i = 0; i < 8; i++) { acc[2*i] = lo2(acc2[i]); acc[2*i+1] = hi2(acc2[i]); }

    __syncthreads();
    if (cq >= 2) {
        float* dst = red + ((cq - 2) * 64 + g) * 17;
        #pragma unroll
        for (int i = 0; i < 16; i++) dst[i] = acc[i];
    }
    __syncthreads();
    if (cq < 2) {
        const float* src = red + (cq * 64 + g) * 17;
        #pragma unroll
        for (int i = 0; i < 16; i++) acc[i] += src[i];
    }
    __syncthreads();
    if (cq == 1) {
        float* dst = red + g * 17;
        #pragma unroll
        for (int i = 0; i < 16; i++) dst[i] = acc[i];
    }
    __syncthreads();
    if (cq == 0) {
        const float* src = red + g * 17;
        #pragma unroll
        for (int i = 0; i < 16; i++) {
            int oc = og * 16 + i;
            out[oc * NPOS + p] = acc[i] + src[i] + bmain[oc];
        }
    }
}

// ---------------------------------------------------------------------------
// K4a: per-channel mean/var -> scale/shift.  K4b: normalize + ReLU in place.
// ---------------------------------------------------------------------------
__global__ void __launch_bounds__(1024) k_bnstat(const float* __restrict__ out,
                                                 const float* __restrict__ gamma,
                                                 const float* __restrict__ beta) {
    __shared__ float ssum[1024], ssq[1024];
    int ch = blockIdx.x;
    const float* base = out + ch * NPOS;
    float s = 0.f, sq = 0.f;
    for (int i = threadIdx.x; i < NPOS; i += 1024) {
        float v = base[i];
        s += v; sq += v * v;
    }
    ssum[threadIdx.x] = s; ssq[threadIdx.x] = sq;
    __syncthreads();
    for (int st = 512; st > 0; st >>= 1) {
        if (threadIdx.x < st) {
            ssum[threadIdx.x] += ssum[threadIdx.x + st];
            ssq[threadIdx.x]  += ssq[threadIdx.x + st];
        }
        __syncthreads();
    }
    if (threadIdx.x == 0) {
        float mean = ssum[0] * (1.f / (float)NPOS);
        float var  = ssq[0] * (1.f / (float)NPOS) - mean * mean;
        float inv  = rsqrtf(var + 1e-5f);
        float a = gamma[ch] * inv;
        g_scale[ch] = a;
        g_shift[ch] = beta[ch] - mean * a;
    }
}

__global__ void k_bnapply(float* __restrict__ out) {
    int idx = blockIdx.x * 256 + threadIdx.x;
    int ch = idx >> 15;
    float v = out[idx] * g_scale[ch] + g_shift[ch];
    out[idx] = fmaxf(v, 0.f);
}

extern "C" void kernel_launch(void* const* d_in, const int* in_sizes, int n_in,
                              void* d_out, int out_size) {
    const float* x     = (const float*)d_in[0];   // (1,64,16,16,16)
    const float* w_off = (const float*)d_in[1];   // (81,64,3,3,3)
    const float* b_off = (const float*)d_in[2];   // (81,)
    const float* w     = (const float*)d_in[3];   // (32,64,3,3,3)
    const float* b     = (const float*)d_in[4];   // (32,)
    const float* gamma = (const float*)d_in[5];   // (32,)
    const float* beta  = (const float*)d_in[6];   // (32,)
    float* out = (float*)d_out;                   // (1,32,32,32,32)

    k_wT<<<(27 * CIN * COUT + 255) / 256, 256>>>(w);
    k_weff<<<(8 * CIN * 8 * OPAD + 255) / 256, 256>>>(w_off);
    k_offconv<<<384, 128>>>(x, b_off);
    k_deform<<<1024, 256>>>(x, b, out);
    k_bnstat<<<COUT, 1024>>>(out, gamma, beta);
    k_bnapply<<<4096, 256>>>(out);
}

// round 14
// speedup vs baseline: 1.1179x; 1.1179x over previous
#include <cuda_runtime.h>
#include <math.h>

#define NPOS 32768      // 32^3 fine positions
#define NCELL 4096      // 16^3 coarse cells
#define CIN 64
#define COFF 81         // 3 * 27 offset channels
#define COUT 32
#define CCHUNK 16
#define OPAD 84         // 3 sections x 28 (27 padded for f32x2 pairs)

// Scratch (no allocs allowed -> __device__ globals)
__device__ float g_off[COFF * NPOS];            // offset conv output, [ch][pos]
__device__ float g_weff[8 * CIN * 8 * OPAD];    // [par][c][j][osec*28+oo]
__device__ float g_wT[27 * CIN * COUT];         // main weights [tap][c][oc]
__device__ float g_Y[NCELL * 27 * COUT];        // Y[cell][tap][oc], 14 MB
__device__ float g_scale[COUT];
__device__ float g_shift[COUT];

// ---- packed f32x2 helpers -------------------------------------------------
__device__ __forceinline__ unsigned long long pack2(float v) {
    unsigned long long r;
    unsigned u = __float_as_uint(v);
    asm("mov.b64 %0, {%1, %1};" : "=l"(r) : "r"(u));
    return r;
}
__device__ __forceinline__ void fma2(unsigned long long& d,
                                     unsigned long long a,
                                     unsigned long long b) {
    asm("fma.rn.f32x2 %0, %1, %2, %0;" : "+l"(d) : "l"(a), "l"(b));
}
__device__ __forceinline__ float lo2(unsigned long long v) {
    return __uint_as_float((unsigned)(v & 0xffffffffULL));
}
__device__ __forceinline__ float hi2(unsigned long long v) {
    return __uint_as_float((unsigned)(v >> 32));
}

// ---------------------------------------------------------------------------
// K0: transpose main conv weights to [tap][c][oc] (one-time, tiny).
// ---------------------------------------------------------------------------
__global__ void k_wT(const float* __restrict__ wmain) {
    int t = blockIdx.x * blockDim.x + threadIdx.x;
    if (t >= 27 * CIN * COUT) return;
    int oc  = t & 31;
    int c   = (t >> 5) & 63;
    int tap = t >> 11;
    g_wT[t] = wmain[(oc * CIN + c) * 27 + tap];
}

// ---------------------------------------------------------------------------
// K1: parity-combined effective weights, [par][c][j][osec*28+oo] padded.
// ---------------------------------------------------------------------------
__global__ void k_weff(const float* __restrict__ w_off) {
    int t = blockIdx.x * blockDim.x + threadIdx.x;
    if (t >= 8 * CIN * 8 * OPAD) return;
    int o84  = t % OPAD;
    int j    = (t / OPAD) & 7;
    int c    = (t / (OPAD * 8)) & 63;
    int par  = t / (OPAD * 8 * CIN);
    int osec = o84 / 28, oo = o84 % 28;
    if (oo >= 27) { g_weff[t] = 0.f; return; }
    int o = osec * 27 + oo;
    int pd = (par >> 2) & 1, ph = (par >> 1) & 1, pw = par & 1;
    int jd = (j >> 2) & 1,  jh = (j >> 1) & 1,  jw = j & 1;
    int sd = jd * (1 + pd), nd = (pd != jd) ? 2 : 1;
    int sh = jh * (1 + ph), nh = (ph != jh) ? 2 : 1;
    int sw = jw * (1 + pw), nw = (pw != jw) ? 2 : 1;
    const float* wb = w_off + (o * CIN + c) * 27;
    float s = 0.f;
    for (int a = 0; a < nd; a++)
        for (int bq = 0; bq < nh; bq++)
            for (int cc = 0; cc < nw; cc++)
                s += wb[(sd + a) * 9 + (sh + bq) * 3 + (sw + cc)];
    g_weff[t] = s;
}

// ---------------------------------------------------------------------------
// K2: offset conv (R12 version): 2-position blocking + 3-way osec split +
// f32x2. grid = 384, 128 thr.
// ---------------------------------------------------------------------------
__global__ void __launch_bounds__(128) k_offconv(const float* __restrict__ x,
                                                 const float* __restrict__ b_off) {
    __shared__ __align__(16) float sw[CCHUNK * 8 * 28];   // 14.3 KB
    int bid  = blockIdx.x;
    int par  = bid / 48;
    int rest = bid % 48;
    int tile = rest / 3;
    int osec = rest % 3;
    int ti   = threadIdx.x;
    int q0 = tile * 256 + ti;                 // and q0 + 128
    int pd = (par >> 2) & 1, ph = (par >> 1) & 1, pw = par & 1;

    int sp[2][8]; float msk[2][8];
    #pragma unroll
    for (int s = 0; s < 2; s++) {
        int q = q0 + s * 128;
        int qw = q & 15, qh = (q >> 4) & 15, qd = q >> 8;
        #pragma unroll
        for (int j = 0; j < 8; j++) {
            int cd = qd + pd - 1 + ((j >> 2) & 1);
            int ch = qh + ph - 1 + ((j >> 1) & 1);
            int cw = qw + pw - 1 + (j & 1);
            bool v = (unsigned)cd < 16u && (unsigned)ch < 16u && (unsigned)cw < 16u;
            sp[s][j]  = v ? ((cd * 16 + ch) * 16 + cw) : 0;
            msk[s][j] = v ? 1.f : 0.f;
        }
    }

    unsigned long long acc[2][14];
    #pragma unroll
    for (int s = 0; s < 2; s++)
        #pragma unroll
        for (int i = 0; i < 14; i++) acc[s][i] = 0ULL;

    #pragma unroll 1
    for (int c0 = 0; c0 < CIN; c0 += CCHUNK) {
        __syncthreads();
        for (int i = ti; i < CCHUNK * 8 * 28; i += 128) {
            int cc = i / (8 * 28);
            int ii = i % (8 * 28);
            int j  = ii / 28, oo = ii % 28;
            sw[i] = g_weff[(((size_t)(par * CIN + c0 + cc)) * 8 + j) * OPAD + osec * 28 + oo];
        }
        __syncthreads();
        #pragma unroll 1
        for (int cc = 0; cc < CCHUNK; cc++) {
            const float* xb = x + (c0 + cc) * NCELL;
            float xv[2][8];
            #pragma unroll
            for (int s = 0; s < 2; s++)
                #pragma unroll
                for (int j = 0; j < 8; j++)
                    xv[s][j] = msk[s][j] * __ldg(&xb[sp[s][j]]);
            #pragma unroll
            for (int j = 0; j < 8; j++) {
                unsigned long long x0 = pack2(xv[0][j]);
                unsigned long long x1 = pack2(xv[1][j]);
                const ulonglong2* wr = (const ulonglong2*)(sw + (cc * 8 + j) * 28);
                #pragma unroll
                for (int op = 0; op < 7; op++) {
                    ulonglong2 wp = wr[op];
                    fma2(acc[0][2*op],   x0, wp.x);
                    fma2(acc[0][2*op+1], x0, wp.y);
                    fma2(acc[1][2*op],   x1, wp.x);
                    fma2(acc[1][2*op+1], x1, wp.y);
                }
            }
        }
    }
    #pragma unroll
    for (int s = 0; s < 2; s++) {
        int q = q0 + s * 128;
        int qw = q & 15, qh = (q >> 4) & 15, qd = q >> 8;
        int df = 2*qd + pd, hf = 2*qh + ph, wf = 2*qw + pw;
        int p = (df * 32 + hf) * 32 + wf;
        #pragma unroll
        for (int i = 0; i < 14; i++) {
            int o0 = 2 * i, o1 = 2 * i + 1;
            g_off[(osec * 27 + o0) * NPOS + p] = lo2(acc[s][i]) + b_off[osec * 27 + o0];
            if (o1 < 27)
                g_off[(osec * 27 + o1) * NPOS + p] = hi2(acc[s][i]) + b_off[osec * 27 + o1];
        }
    }
}

// ---------------------------------------------------------------------------
// K3a: Y GEMM. Y[cell][tap][oc] = sum_c x[c][cell] * wT[tap][c][oc].
// Warp = 2 cells, lane = oc. x loads are lane-uniform broadcasts; weight
// loads are 128B coalesced and L1-hot across warps. acc[2][27] in regs.
// grid = 256 blocks x 256 thr (16 cells/block).
// ---------------------------------------------------------------------------
__global__ void __launch_bounds__(256) k_ygemm(const float* __restrict__ x) {
    int lane = threadIdx.x & 31;
    int wrp  = threadIdx.x >> 5;
    int cell0 = blockIdx.x * 16 + wrp * 2;

    float a0[27], a1[27];
    #pragma unroll
    for (int t = 0; t < 27; t++) { a0[t] = 0.f; a1[t] = 0.f; }

    #pragma unroll 4
    for (int c = 0; c < CIN; c++) {
        float x0 = __ldg(&x[c * NCELL + cell0]);
        float x1 = __ldg(&x[c * NCELL + cell0 + 1]);
        const float* wc = g_wT + c * COUT + lane;
        #pragma unroll
        for (int t = 0; t < 27; t++) {
            float w = __ldg(wc + t * (CIN * COUT));
            a0[t] += x0 * w;
            a1[t] += x1 * w;
        }
    }
    float* y0 = g_Y + (size_t)cell0 * 27 * COUT + lane;
    #pragma unroll
    for (int t = 0; t < 27; t++) {
        y0[t * COUT]             = a0[t];
        y0[27 * COUT + t * COUT] = a1[t];
    }
}

// ---------------------------------------------------------------------------
// K3b: scatter. Warp = one fine position, lane = oc. Per tap: corner
// dedup (all math warp-uniform), each active corner reads one contiguous
// 128B row Y[cell][tap][:] (1 wavefront) and does one FMA per lane.
// grid = 4096 blocks x 256 thr.
// ---------------------------------------------------------------------------
__global__ void __launch_bounds__(256) k_scatter(const float* __restrict__ bmain,
                                                 float* __restrict__ out) {
    int lane = threadIdx.x & 31;
    int wrp  = threadIdx.x >> 5;
    int p = blockIdx.x * 8 + wrp;
    int wf = p & 31, hf = (p >> 5) & 31, df = p >> 10;

    float acc = 0.f;

    #pragma unroll 1
    for (int tap = 0; tap < 27; tap++) {
        int kd = tap / 9, kh = (tap / 3) % 3, kw = tap % 3;
        float pdc = (float)(df + kd - 1) + __ldg(&g_off[(tap * 3 + 0) * NPOS + p]);
        float phc = (float)(hf + kh - 1) + __ldg(&g_off[(tap * 3 + 1) * NPOS + p]);
        float pwc = (float)(wf + kw - 1) + __ldg(&g_off[(tap * 3 + 2) * NPOS + p]);
        float fd0 = floorf(pdc), fh0 = floorf(phc), fw0 = floorf(pwc);
        int id0 = (int)fd0, ih0 = (int)fh0, iw0 = (int)fw0;
        float fd = pdc - fd0, fh = phc - fh0, fw = pwc - fw0;

        int cD[2], cH[2], cW[2]; float wD[2], wH[2], wW[2];
        cD[0] = id0 >> 1; cD[1] = (id0 + 1) >> 1;
        cH[0] = ih0 >> 1; cH[1] = (ih0 + 1) >> 1;
        cW[0] = iw0 >> 1; cW[1] = (iw0 + 1) >> 1;
        bool ed = !(id0 & 1), eh = !(ih0 & 1), ew = !(iw0 & 1);
        wD[0] = ed ? 1.f : 1.f - fd;  wD[1] = ed ? 0.f : fd;
        wH[0] = eh ? 1.f : 1.f - fh;  wH[1] = eh ? 0.f : fh;
        wW[0] = ew ? 1.f : 1.f - fw;  wW[1] = ew ? 0.f : fw;
        if ((unsigned)cD[0] >= 16u) wD[0] = 0.f;
        if ((unsigned)cD[1] >= 16u) wD[1] = 0.f;
        if ((unsigned)cH[0] >= 16u) wH[0] = 0.f;
        if ((unsigned)cH[1] >= 16u) wH[1] = 0.f;
        if ((unsigned)cW[0] >= 16u) wW[0] = 0.f;
        if ((unsigned)cW[1] >= 16u) wW[1] = 0.f;

        const float* ybase = g_Y + tap * COUT + lane;
        #pragma unroll
        for (int jd = 0; jd < 2; jd++)
        #pragma unroll
        for (int jh = 0; jh < 2; jh++)
        #pragma unroll
        for (int jw = 0; jw < 2; jw++) {
            float wj = wD[jd] * wH[jh] * wW[jw];
            if (wj != 0.f) {   // warp-uniform branch
                int cell = (cD[jd] * 16 + cH[jh]) * 16 + cW[jw];
                acc += wj * __ldg(ybase + (size_t)cell * (27 * COUT));
            }
        }
    }
    out[lane * NPOS + p] = acc + bmain[lane];
}

// ---------------------------------------------------------------------------
// K4a: per-channel mean/var -> scale/shift.  K4b: normalize + ReLU in place.
// ---------------------------------------------------------------------------
__global__ void __launch_bounds__(1024) k_bnstat(const float* __restrict__ out,
                                                 const float* __restrict__ gamma,
                                                 const float* __restrict__ beta) {
    __shared__ float ssum[1024], ssq[1024];
    int ch = blockIdx.x;
    const float* base = out + ch * NPOS;
    float s = 0.f, sq = 0.f;
    for (int i = threadIdx.x; i < NPOS; i += 1024) {
        float v = base[i];
        s += v; sq += v * v;
    }
    ssum[threadIdx.x] = s; ssq[threadIdx.x] = sq;
    __syncthreads();
    for (int st = 512; st > 0; st >>= 1) {
        if (threadIdx.x < st) {
            ssum[threadIdx.x] += ssum[threadIdx.x + st];
            ssq[threadIdx.x]  += ssq[threadIdx.x + st];
        }
        __syncthreads();
    }
    if (threadIdx.x == 0) {
        float mean = ssum[0] * (1.f / (float)NPOS);
        float var  = ssq[0] * (1.f / (float)NPOS) - mean * mean;
        float inv  = rsqrtf(var + 1e-5f);
        float a = gamma[ch] * inv;
        g_scale[ch] = a;
        g_shift[ch] = beta[ch] - mean * a;
    }
}

__global__ void k_bnapply(float* __restrict__ out) {
    int idx = blockIdx.x * 256 + threadIdx.x;
    int ch = idx >> 15;
    float v = out[idx] * g_scale[ch] + g_shift[ch];
    out[idx] = fmaxf(v, 0.f);
}

extern "C" void kernel_launch(void* const* d_in, const int* in_sizes, int n_in,
                              void* d_out, int out_size) {
    const float* x     = (const float*)d_in[0];   // (1,64,16,16,16)
    const float* w_off = (const float*)d_in[1];   // (81,64,3,3,3)
    const float* b_off = (const float*)d_in[2];   // (81,)
    const float* w     = (const float*)d_in[3];   // (32,64,3,3,3)
    const float* b     = (const float*)d_in[4];   // (32,)
    const float* gamma = (const float*)d_in[5];   // (32,)
    const float* beta  = (const float*)d_in[6];   // (32,)
    float* out = (float*)d_out;                   // (1,32,32,32,32)

    k_wT<<<(27 * CIN * COUT + 255) / 256, 256>>>(w);
    k_weff<<<(8 * CIN * 8 * OPAD + 255) / 256, 256>>>(w_off);
    k_offconv<<<384, 128>>>(x, b_off);
    k_ygemm<<<256, 256>>>(x);
    k_scatter<<<4096, 256>>>(b, out);
    k_bnstat<<<COUT, 1024>>>(out, gamma, beta);
    k_bnapply<<<4096, 256>>>(out);
}

// round 16
// speedup vs baseline: 1.8388x; 1.6448x over previous
#include <cuda_runtime.h>
#include <math.h>

#define NPOS 32768      // 32^3 fine positions
#define NCELL 4096      // 16^3 coarse cells
#define CIN 64
#define COFF 81         // 3 * 27 offset channels
#define COUT 32
#define CCHUNK 16
#define OPAD 84         // 3 sections x 28 (27 padded for f32x2 pairs)

// Scratch (no allocs allowed -> __device__ globals)
__device__ float g_off[COFF * NPOS];            // offset conv output, [ch][pos]
__device__ float g_weff[8 * CIN * 8 * OPAD];    // [par][c][j][osec*28+oo]
__device__ float g_wT[27 * CIN * COUT];         // main weights [tap][c][oc]
__device__ float g_Y[NCELL * 27 * COUT];        // Y[cell][tap][oc], 14 MB
__device__ float g_scale[COUT];
__device__ float g_shift[COUT];

// ---- packed f32x2 helpers -------------------------------------------------
__device__ __forceinline__ unsigned long long pack2(float v) {
    unsigned long long r;
    unsigned u = __float_as_uint(v);
    asm("mov.b64 %0, {%1, %1};" : "=l"(r) : "r"(u));
    return r;
}
__device__ __forceinline__ void fma2(unsigned long long& d,
                                     unsigned long long a,
                                     unsigned long long b) {
    asm("fma.rn.f32x2 %0, %1, %2, %0;" : "+l"(d) : "l"(a), "l"(b));
}
__device__ __forceinline__ float lo2(unsigned long long v) {
    return __uint_as_float((unsigned)(v & 0xffffffffULL));
}
__device__ __forceinline__ float hi2(unsigned long long v) {
    return __uint_as_float((unsigned)(v >> 32));
}

// ---------------------------------------------------------------------------
// K0: transpose main conv weights to [tap][c][oc] (one-time, tiny).
// ---------------------------------------------------------------------------
__global__ void k_wT(const float* __restrict__ wmain) {
    int t = blockIdx.x * blockDim.x + threadIdx.x;
    if (t >= 27 * CIN * COUT) return;
    int oc  = t & 31;
    int c   = (t >> 5) & 63;
    int tap = t >> 11;
    g_wT[t] = wmain[(oc * CIN + c) * 27 + tap];
}

// ---------------------------------------------------------------------------
// K1: parity-combined effective weights, [par][c][j][osec*28+oo] padded.
// ---------------------------------------------------------------------------
__global__ void k_weff(const float* __restrict__ w_off) {
    int t = blockIdx.x * blockDim.x + threadIdx.x;
    if (t >= 8 * CIN * 8 * OPAD) return;
    int o84  = t % OPAD;
    int j    = (t / OPAD) & 7;
    int c    = (t / (OPAD * 8)) & 63;
    int par  = t / (OPAD * 8 * CIN);
    int osec = o84 / 28, oo = o84 % 28;
    if (oo >= 27) { g_weff[t] = 0.f; return; }
    int o = osec * 27 + oo;
    int pd = (par >> 2) & 1, ph = (par >> 1) & 1, pw = par & 1;
    int jd = (j >> 2) & 1,  jh = (j >> 1) & 1,  jw = j & 1;
    int sd = jd * (1 + pd), nd = (pd != jd) ? 2 : 1;
    int sh = jh * (1 + ph), nh = (ph != jh) ? 2 : 1;
    int sw = jw * (1 + pw), nw = (pw != jw) ? 2 : 1;
    const float* wb = w_off + (o * CIN + c) * 27;
    float s = 0.f;
    for (int a = 0; a < nd; a++)
        for (int bq = 0; bq < nh; bq++)
            for (int cc = 0; cc < nw; cc++)
                s += wb[(sd + a) * 9 + (sh + bq) * 3 + (sw + cc)];
    g_weff[t] = s;
}

// ---------------------------------------------------------------------------
// K2: offset conv (R12 version): 2-position blocking + 3-way osec split +
// f32x2. grid = 384, 128 thr.
// ---------------------------------------------------------------------------
__global__ void __launch_bounds__(128) k_offconv(const float* __restrict__ x,
                                                 const float* __restrict__ b_off) {
    __shared__ __align__(16) float sw[CCHUNK * 8 * 28];   // 14.3 KB
    int bid  = blockIdx.x;
    int par  = bid / 48;
    int rest = bid % 48;
    int tile = rest / 3;
    int osec = rest % 3;
    int ti   = threadIdx.x;
    int q0 = tile * 256 + ti;                 // and q0 + 128
    int pd = (par >> 2) & 1, ph = (par >> 1) & 1, pw = par & 1;

    int sp[2][8]; float msk[2][8];
    #pragma unroll
    for (int s = 0; s < 2; s++) {
        int q = q0 + s * 128;
        int qw = q & 15, qh = (q >> 4) & 15, qd = q >> 8;
        #pragma unroll
        for (int j = 0; j < 8; j++) {
            int cd = qd + pd - 1 + ((j >> 2) & 1);
            int ch = qh + ph - 1 + ((j >> 1) & 1);
            int cw = qw + pw - 1 + (j & 1);
            bool v = (unsigned)cd < 16u && (unsigned)ch < 16u && (unsigned)cw < 16u;
            sp[s][j]  = v ? ((cd * 16 + ch) * 16 + cw) : 0;
            msk[s][j] = v ? 1.f : 0.f;
        }
    }

    unsigned long long acc[2][14];
    #pragma unroll
    for (int s = 0; s < 2; s++)
        #pragma unroll
        for (int i = 0; i < 14; i++) acc[s][i] = 0ULL;

    #pragma unroll 1
    for (int c0 = 0; c0 < CIN; c0 += CCHUNK) {
        __syncthreads();
        for (int i = ti; i < CCHUNK * 8 * 28; i += 128) {
            int cc = i / (8 * 28);
            int ii = i % (8 * 28);
            int j  = ii / 28, oo = ii % 28;
            sw[i] = g_weff[(((size_t)(par * CIN + c0 + cc)) * 8 + j) * OPAD + osec * 28 + oo];
        }
        __syncthreads();
        #pragma unroll 1
        for (int cc = 0; cc < CCHUNK; cc++) {
            const float* xb = x + (c0 + cc) * NCELL;
            float xv[2][8];
            #pragma unroll
            for (int s = 0; s < 2; s++)
                #pragma unroll
                for (int j = 0; j < 8; j++)
                    xv[s][j] = msk[s][j] * __ldg(&xb[sp[s][j]]);
            #pragma unroll
            for (int j = 0; j < 8; j++) {
                unsigned long long x0 = pack2(xv[0][j]);
                unsigned long long x1 = pack2(xv[1][j]);
                const ulonglong2* wr = (const ulonglong2*)(sw + (cc * 8 + j) * 28);
                #pragma unroll
                for (int op = 0; op < 7; op++) {
                    ulonglong2 wp = wr[op];
                    fma2(acc[0][2*op],   x0, wp.x);
                    fma2(acc[0][2*op+1], x0, wp.y);
                    fma2(acc[1][2*op],   x1, wp.x);
                    fma2(acc[1][2*op+1], x1, wp.y);
                }
            }
        }
    }
    #pragma unroll
    for (int s = 0; s < 2; s++) {
        int q = q0 + s * 128;
        int qw = q & 15, qh = (q >> 4) & 15, qd = q >> 8;
        int df = 2*qd + pd, hf = 2*qh + ph, wf = 2*qw + pw;
        int p = (df * 32 + hf) * 32 + wf;
        #pragma unroll
        for (int i = 0; i < 14; i++) {
            int o0 = 2 * i, o1 = 2 * i + 1;
            g_off[(osec * 27 + o0) * NPOS + p] = lo2(acc[s][i]) + b_off[osec * 27 + o0];
            if (o1 < 27)
                g_off[(osec * 27 + o1) * NPOS + p] = hi2(acc[s][i]) + b_off[osec * 27 + o1];
        }
    }
}

// ---------------------------------------------------------------------------
// K3a: Y GEMM v3, tap-outer. Warp = one cell, lane = oc. The cell's 64 x
// values live in (warp-uniform) registers; per tap the weight slice is
// staged in smem (8 KB broadcast-read). grid = 512 x 256 thr.
// ---------------------------------------------------------------------------
__global__ void __launch_bounds__(256) k_ygemm(const float* __restrict__ x) {
    __shared__ __align__(16) float ws[CIN * COUT];   // [c][oc], 8 KB
    int tid  = threadIdx.x;
    int lane = tid & 31;
    int wrp  = tid >> 5;
    int cell = blockIdx.x * 8 + wrp;

    float xr[CIN];
    #pragma unroll
    for (int c = 0; c < CIN; c++) xr[c] = __ldg(&x[c * NCELL + cell]);

    float* ydst = g_Y + (size_t)cell * (27 * COUT) + lane;

    #pragma unroll 1
    for (int tap = 0; tap < 27; tap++) {
        __syncthreads();
        {
            const float4* src = (const float4*)(g_wT + tap * CIN * COUT);
            float4* dst = (float4*)ws;
            dst[tid]       = src[tid];
            dst[tid + 256] = src[tid + 256];
        }
        __syncthreads();

        float acc = 0.f;
        #pragma unroll
        for (int c = 0; c < CIN; c++)
            acc += xr[c] * ws[c * COUT + lane];
        ydst[tap * COUT] = acc;
    }
}

// ---------------------------------------------------------------------------
// K3b: scatter v2, branchless. Warp = one fine position, lane = oc.
// Per tap: fold corners (dedup + OOB via zero weights, cells clamped so
// every load is in-bounds), then 8 unconditional 128B Y-row loads (MLP 8,
// duplicate rows hit L1) + 8 FMA per lane. grid = 4096 x 256 thr.
// ---------------------------------------------------------------------------
__global__ void __launch_bounds__(256) k_scatter(const float* __restrict__ bmain,
                                                 float* __restrict__ out) {
    int lane = threadIdx.x & 31;
    int wrp  = threadIdx.x >> 5;
    int p = blockIdx.x * 8 + wrp;
    int wf = p & 31, hf = (p >> 5) & 31, df = p >> 10;

    float acc = 0.f;

    #pragma unroll 1
    for (int tap = 0; tap < 27; tap++) {
        int kd = tap / 9, kh = (tap / 3) % 3, kw = tap % 3;
        float pdc = (float)(df + kd - 1) + __ldg(&g_off[(tap * 3 + 0) * NPOS + p]);
        float phc = (float)(hf + kh - 1) + __ldg(&g_off[(tap * 3 + 1) * NPOS + p]);
        float pwc = (float)(wf + kw - 1) + __ldg(&g_off[(tap * 3 + 2) * NPOS + p]);
        float fd0 = floorf(pdc), fh0 = floorf(phc), fw0 = floorf(pwc);
        int id0 = (int)fd0, ih0 = (int)fh0, iw0 = (int)fw0;
        float fd = pdc - fd0, fh = phc - fh0, fw = pwc - fw0;

        int cD[2], cH[2], cW[2]; float wD[2], wH[2], wW[2];
        cD[0] = id0 >> 1; cD[1] = (id0 + 1) >> 1;
        cH[0] = ih0 >> 1; cH[1] = (ih0 + 1) >> 1;
        cW[0] = iw0 >> 1; cW[1] = (iw0 + 1) >> 1;
        bool ed = !(id0 & 1), eh = !(ih0 & 1), ew = !(iw0 & 1);
        wD[0] = ed ? 1.f : 1.f - fd;  wD[1] = ed ? 0.f : fd;
        wH[0] = eh ? 1.f : 1.f - fh;  wH[1] = eh ? 0.f : fh;
        wW[0] = ew ? 1.f : 1.f - fw;  wW[1] = ew ? 0.f : fw;
        #pragma unroll
        for (int k = 0; k < 2; k++) {
            if ((unsigned)cD[k] >= 16u) { wD[k] = 0.f; cD[k] = min(15, max(0, cD[k])); }
            if ((unsigned)cH[k] >= 16u) { wH[k] = 0.f; cH[k] = min(15, max(0, cH[k])); }
            if ((unsigned)cW[k] >= 16u) { wW[k] = 0.f; cW[k] = min(15, max(0, cW[k])); }
        }

        const float* ybase = g_Y + tap * COUT + lane;
        // 8 unconditional independent loads, weights kill dup/OOB lanes
        float v[8]; float wj[8];
        #pragma unroll
        for (int j = 0; j < 8; j++) {
            int jd = (j >> 2) & 1, jh = (j >> 1) & 1, jw = j & 1;
            int cell = (cD[jd] * 16 + cH[jh]) * 16 + cW[jw];
            wj[j] = wD[jd] * wH[jh] * wW[jw];
            v[j]  = __ldg(ybase + (size_t)cell * (27 * COUT));
        }
        #pragma unroll
        for (int j = 0; j < 8; j++) acc += wj[j] * v[j];
    }
    out[lane * NPOS + p] = acc + bmain[lane];
}

// ---------------------------------------------------------------------------
// K4a: per-channel mean/var -> scale/shift.  K4b: normalize + ReLU in place.
// ---------------------------------------------------------------------------
__global__ void __launch_bounds__(1024) k_bnstat(const float* __restrict__ out,
                                                 const float* __restrict__ gamma,
                                                 const float* __restrict__ beta) {
    __shared__ float ssum[1024], ssq[1024];
    int ch = blockIdx.x;
    const float* base = out + ch * NPOS;
    float s = 0.f, sq = 0.f;
    for (int i = threadIdx.x; i < NPOS; i += 1024) {
        float v = base[i];
        s += v; sq += v * v;
    }
    ssum[threadIdx.x] = s; ssq[threadIdx.x] = sq;
    __syncthreads();
    for (int st = 512; st > 0; st >>= 1) {
        if (threadIdx.x < st) {
            ssum[threadIdx.x] += ssum[threadIdx.x + st];
            ssq[threadIdx.x]  += ssq[threadIdx.x + st];
        }
        __syncthreads();
    }
    if (threadIdx.x == 0) {
        float mean = ssum[0] * (1.f / (float)NPOS);
        float var  = ssq[0] * (1.f / (float)NPOS) - mean * mean;
        float inv  = rsqrtf(var + 1e-5f);
        float a = gamma[ch] * inv;
        g_scale[ch] = a;
        g_shift[ch] = beta[ch] - mean * a;
    }
}

__global__ void k_bnapply(float* __restrict__ out) {
    int idx = blockIdx.x * 256 + threadIdx.x;
    int ch = idx >> 15;
    float v = out[idx] * g_scale[ch] + g_shift[ch];
    out[idx] = fmaxf(v, 0.f);
}

extern "C" void kernel_launch(void* const* d_in, const int* in_sizes, int n_in,
                              void* d_out, int out_size) {
    const float* x     = (const float*)d_in[0];   // (1,64,16,16,16)
    const float* w_off = (const float*)d_in[1];   // (81,64,3,3,3)
    const float* b_off = (const float*)d_in[2];   // (81,)
    const float* w     = (const float*)d_in[3];   // (32,64,3,3,3)
    const float* b     = (const float*)d_in[4];   // (32,)
    const float* gamma = (const float*)d_in[5];   // (32,)
    const float* beta  = (const float*)d_in[6];   // (32,)
    float* out = (float*)d_out;                   // (1,32,32,32,32)

    k_wT<<<(27 * CIN * COUT + 255) / 256, 256>>>(w);
    k_weff<<<(8 * CIN * 8 * OPAD + 255) / 256, 256>>>(w_off);
    k_offconv<<<384, 128>>>(x, b_off);
    k_ygemm<<<512, 256>>>(x);
    k_scatter<<<4096, 256>>>(b, out);
    k_bnstat<<<COUT, 1024>>>(out, gamma, beta);
    k_bnapply<<<4096, 256>>>(out);
}

// round 17
// speedup vs baseline: 2.0625x; 1.1217x over previous
#include <cuda_runtime.h>
#include <math.h>

#define NPOS 32768      // 32^3 fine positions
#define NCELL 4096      // 16^3 coarse cells
#define CIN 64
#define COFF 81         // 3 * 27 offset channels
#define COUT 32
#define CCHUNK 16
#define OPAD 84         // 3 sections x 28 (27 padded for f32x2 pairs)

// Scratch (no allocs allowed -> __device__ globals)
__device__ float g_off[COFF * NPOS];            // offset conv output, [ch][pos]
__device__ float g_weff[8 * CIN * 8 * OPAD];    // [par][c][j][osec*28+oo]
__device__ float g_wT[27 * CIN * COUT];         // main weights [tap][c][oc]
__device__ float g_Y[NCELL * 27 * COUT];        // Y[cell][tap][oc], 14 MB
__device__ float g_scale[COUT];
__device__ float g_shift[COUT];

// ---- packed f32x2 helpers -------------------------------------------------
__device__ __forceinline__ unsigned long long pack2(float v) {
    unsigned long long r;
    unsigned u = __float_as_uint(v);
    asm("mov.b64 %0, {%1, %1};" : "=l"(r) : "r"(u));
    return r;
}
__device__ __forceinline__ void fma2(unsigned long long& d,
                                     unsigned long long a,
                                     unsigned long long b) {
    asm("fma.rn.f32x2 %0, %1, %2, %0;" : "+l"(d) : "l"(a), "l"(b));
}
__device__ __forceinline__ float lo2(unsigned long long v) {
    return __uint_as_float((unsigned)(v & 0xffffffffULL));
}
__device__ __forceinline__ float hi2(unsigned long long v) {
    return __uint_as_float((unsigned)(v >> 32));
}

// ---------------------------------------------------------------------------
// K0: transpose main conv weights to [tap][c][oc] (one-time, tiny).
// ---------------------------------------------------------------------------
__global__ void k_wT(const float* __restrict__ wmain) {
    int t = blockIdx.x * blockDim.x + threadIdx.x;
    if (t >= 27 * CIN * COUT) return;
    int oc  = t & 31;
    int c   = (t >> 5) & 63;
    int tap = t >> 11;
    g_wT[t] = wmain[(oc * CIN + c) * 27 + tap];
}

// ---------------------------------------------------------------------------
// K1: parity-combined effective weights, [par][c][j][osec*28+oo] padded.
// ---------------------------------------------------------------------------
__global__ void k_weff(const float* __restrict__ w_off) {
    int t = blockIdx.x * blockDim.x + threadIdx.x;
    if (t >= 8 * CIN * 8 * OPAD) return;
    int o84  = t % OPAD;
    int j    = (t / OPAD) & 7;
    int c    = (t / (OPAD * 8)) & 63;
    int par  = t / (OPAD * 8 * CIN);
    int osec = o84 / 28, oo = o84 % 28;
    if (oo >= 27) { g_weff[t] = 0.f; return; }
    int o = osec * 27 + oo;
    int pd = (par >> 2) & 1, ph = (par >> 1) & 1, pw = par & 1;
    int jd = (j >> 2) & 1,  jh = (j >> 1) & 1,  jw = j & 1;
    int sd = jd * (1 + pd), nd = (pd != jd) ? 2 : 1;
    int sh = jh * (1 + ph), nh = (ph != jh) ? 2 : 1;
    int sw = jw * (1 + pw), nw = (pw != jw) ? 2 : 1;
    const float* wb = w_off + (o * CIN + c) * 27;
    float s = 0.f;
    for (int a = 0; a < nd; a++)
        for (int bq = 0; bq < nh; bq++)
            for (int cc = 0; cc < nw; cc++)
                s += wb[(sd + a) * 9 + (sh + bq) * 3 + (sw + cc)];
    g_weff[t] = s;
}

// ---------------------------------------------------------------------------
// K2: offset conv (R12 version): 2-position blocking + 3-way osec split +
// f32x2. grid = 384, 128 thr.
// ---------------------------------------------------------------------------
__global__ void __launch_bounds__(128) k_offconv(const float* __restrict__ x,
                                                 const float* __restrict__ b_off) {
    __shared__ __align__(16) float sw[CCHUNK * 8 * 28];   // 14.3 KB
    int bid  = blockIdx.x;
    int par  = bid / 48;
    int rest = bid % 48;
    int tile = rest / 3;
    int osec = rest % 3;
    int ti   = threadIdx.x;
    int q0 = tile * 256 + ti;                 // and q0 + 128
    int pd = (par >> 2) & 1, ph = (par >> 1) & 1, pw = par & 1;

    int sp[2][8]; float msk[2][8];
    #pragma unroll
    for (int s = 0; s < 2; s++) {
        int q = q0 + s * 128;
        int qw = q & 15, qh = (q >> 4) & 15, qd = q >> 8;
        #pragma unroll
        for (int j = 0; j < 8; j++) {
            int cd = qd + pd - 1 + ((j >> 2) & 1);
            int ch = qh + ph - 1 + ((j >> 1) & 1);
            int cw = qw + pw - 1 + (j & 1);
            bool v = (unsigned)cd < 16u && (unsigned)ch < 16u && (unsigned)cw < 16u;
            sp[s][j]  = v ? ((cd * 16 + ch) * 16 + cw) : 0;
            msk[s][j] = v ? 1.f : 0.f;
        }
    }

    unsigned long long acc[2][14];
    #pragma unroll
    for (int s = 0; s < 2; s++)
        #pragma unroll
        for (int i = 0; i < 14; i++) acc[s][i] = 0ULL;

    #pragma unroll 1
    for (int c0 = 0; c0 < CIN; c0 += CCHUNK) {
        __syncthreads();
        for (int i = ti; i < CCHUNK * 8 * 28; i += 128) {
            int cc = i / (8 * 28);
            int ii = i % (8 * 28);
            int j  = ii / 28, oo = ii % 28;
            sw[i] = g_weff[(((size_t)(par * CIN + c0 + cc)) * 8 + j) * OPAD + osec * 28 + oo];
        }
        __syncthreads();
        #pragma unroll 1
        for (int cc = 0; cc < CCHUNK; cc++) {
            const float* xb = x + (c0 + cc) * NCELL;
            float xv[2][8];
            #pragma unroll
            for (int s = 0; s < 2; s++)
                #pragma unroll
                for (int j = 0; j < 8; j++)
                    xv[s][j] = msk[s][j] * __ldg(&xb[sp[s][j]]);
            #pragma unroll
            for (int j = 0; j < 8; j++) {
                unsigned long long x0 = pack2(xv[0][j]);
                unsigned long long x1 = pack2(xv[1][j]);
                const ulonglong2* wr = (const ulonglong2*)(sw + (cc * 8 + j) * 28);
                #pragma unroll
                for (int op = 0; op < 7; op++) {
                    ulonglong2 wp = wr[op];
                    fma2(acc[0][2*op],   x0, wp.x);
                    fma2(acc[0][2*op+1], x0, wp.y);
                    fma2(acc[1][2*op],   x1, wp.x);
                    fma2(acc[1][2*op+1], x1, wp.y);
                }
            }
        }
    }
    #pragma unroll
    for (int s = 0; s < 2; s++) {
        int q = q0 + s * 128;
        int qw = q & 15, qh = (q >> 4) & 15, qd = q >> 8;
        int df = 2*qd + pd, hf = 2*qh + ph, wf = 2*qw + pw;
        int p = (df * 32 + hf) * 32 + wf;
        #pragma unroll
        for (int i = 0; i < 14; i++) {
            int o0 = 2 * i, o1 = 2 * i + 1;
            g_off[(osec * 27 + o0) * NPOS + p] = lo2(acc[s][i]) + b_off[osec * 27 + o0];
            if (o1 < 27)
                g_off[(osec * 27 + o1) * NPOS + p] = hi2(acc[s][i]) + b_off[osec * 27 + o1];
        }
    }
}

// ---------------------------------------------------------------------------
// K3a: Y GEMM v4, register-tiled. Block = 16 cells (128 thr, 256 blocks).
// xs[c][cell] (4 KB) staged once; ws[c][oc] (8 KB) staged per tap.
// Thread computes a 2-cell x 2-oc tile: per c-step 2x LDS.64 + 4 FMA.
// ---------------------------------------------------------------------------
__global__ void __launch_bounds__(128) k_ygemm(const float* __restrict__ x) {
    __shared__ __align__(16) float xs[CIN * 16];     // [c][cell], 4 KB
    __shared__ __align__(16) float ws[CIN * COUT];   // [c][oc], 8 KB
    int tid  = threadIdx.x;
    int co   = tid & 15;          // oc pair: oc0 = co*2
    int cl   = tid >> 4;          // cell pair: cell = cl*2, cl*2+1
    int cell0 = blockIdx.x * 16;

    // stage xs: 1024 floats, coalesced over 16-cell rows
    for (int i = tid; i < CIN * 16; i += 128) {
        int c = i >> 4, ci = i & 15;
        xs[i] = __ldg(&x[c * NCELL + cell0 + ci]);
    }

    #pragma unroll 1
    for (int tap = 0; tap < 27; tap++) {
        __syncthreads();
        {   // stage ws: 2048 floats = 512 float4, 4 per thread
            const float4* src = (const float4*)(g_wT + tap * CIN * COUT);
            float4* dst = (float4*)ws;
            #pragma unroll
            for (int i = 0; i < 4; i++) dst[tid + i * 128] = src[tid + i * 128];
        }
        __syncthreads();

        float a00 = 0.f, a01 = 0.f, a10 = 0.f, a11 = 0.f;
        #pragma unroll
        for (int c = 0; c < CIN; c++) {
            float2 xv = *(const float2*)(xs + c * 16 + cl * 2);
            float2 wv = *(const float2*)(ws + c * COUT + co * 2);
            a00 += xv.x * wv.x;  a01 += xv.x * wv.y;
            a10 += xv.y * wv.x;  a11 += xv.y * wv.y;
        }
        size_t base = ((size_t)(cell0 + cl * 2) * 27 + tap) * COUT + co * 2;
        *(float2*)(g_Y + base)             = make_float2(a00, a01);
        *(float2*)(g_Y + base + 27 * COUT) = make_float2(a10, a11);
    }
}

// ---------------------------------------------------------------------------
// K3b: scatter v2, branchless. Warp = one fine position, lane = oc.
// Per tap: fold corners (dedup + OOB via zero weights, cells clamped so
// every load is in-bounds), then 8 unconditional 128B Y-row loads (MLP 8,
// duplicate rows hit L1) + 8 FMA per lane. grid = 4096 x 256 thr.
// ---------------------------------------------------------------------------
__global__ void __launch_bounds__(256) k_scatter(const float* __restrict__ bmain,
                                                 float* __restrict__ out) {
    int lane = threadIdx.x & 31;
    int wrp  = threadIdx.x >> 5;
    int p = blockIdx.x * 8 + wrp;
    int wf = p & 31, hf = (p >> 5) & 31, df = p >> 10;

    float acc = 0.f;

    #pragma unroll 1
    for (int tap = 0; tap < 27; tap++) {
        int kd = tap / 9, kh = (tap / 3) % 3, kw = tap % 3;
        float pdc = (float)(df + kd - 1) + __ldg(&g_off[(tap * 3 + 0) * NPOS + p]);
        float phc = (float)(hf + kh - 1) + __ldg(&g_off[(tap * 3 + 1) * NPOS + p]);
        float pwc = (float)(wf + kw - 1) + __ldg(&g_off[(tap * 3 + 2) * NPOS + p]);
        float fd0 = floorf(pdc), fh0 = floorf(phc), fw0 = floorf(pwc);
        int id0 = (int)fd0, ih0 = (int)fh0, iw0 = (int)fw0;
        float fd = pdc - fd0, fh = phc - fh0, fw = pwc - fw0;

        int cD[2], cH[2], cW[2]; float wD[2], wH[2], wW[2];
        cD[0] = id0 >> 1; cD[1] = (id0 + 1) >> 1;
        cH[0] = ih0 >> 1; cH[1] = (ih0 + 1) >> 1;
        cW[0] = iw0 >> 1; cW[1] = (iw0 + 1) >> 1;
        bool ed = !(id0 & 1), eh = !(ih0 & 1), ew = !(iw0 & 1);
        wD[0] = ed ? 1.f : 1.f - fd;  wD[1] = ed ? 0.f : fd;
        wH[0] = eh ? 1.f : 1.f - fh;  wH[1] = eh ? 0.f : fh;
        wW[0] = ew ? 1.f : 1.f - fw;  wW[1] = ew ? 0.f : fw;
        #pragma unroll
        for (int k = 0; k < 2; k++) {
            if ((unsigned)cD[k] >= 16u) { wD[k] = 0.f; cD[k] = min(15, max(0, cD[k])); }
            if ((unsigned)cH[k] >= 16u) { wH[k] = 0.f; cH[k] = min(15, max(0, cH[k])); }
            if ((unsigned)cW[k] >= 16u) { wW[k] = 0.f; cW[k] = min(15, max(0, cW[k])); }
        }

        const float* ybase = g_Y + tap * COUT + lane;
        // 8 unconditional independent loads, weights kill dup/OOB lanes
        float v[8]; float wj[8];
        #pragma unroll
        for (int j = 0; j < 8; j++) {
            int jd = (j >> 2) & 1, jh = (j >> 1) & 1, jw = j & 1;
            int cell = (cD[jd] * 16 + cH[jh]) * 16 + cW[jw];
            wj[j] = wD[jd] * wH[jh] * wW[jw];
            v[j]  = __ldg(ybase + (size_t)cell * (27 * COUT));
        }
        #pragma unroll
        for (int j = 0; j < 8; j++) acc += wj[j] * v[j];
    }
    out[lane * NPOS + p] = acc + bmain[lane];
}

// ---------------------------------------------------------------------------
// K4a: per-channel mean/var -> scale/shift.  K4b: normalize + ReLU in place.
// ---------------------------------------------------------------------------
__global__ void __launch_bounds__(1024) k_bnstat(const float* __restrict__ out,
                                                 const float* __restrict__ gamma,
                                                 const float* __restrict__ beta) {
    __shared__ float ssum[1024], ssq[1024];
    int ch = blockIdx.x;
    const float* base = out + ch * NPOS;
    float s = 0.f, sq = 0.f;
    for (int i = threadIdx.x; i < NPOS; i += 1024) {
        float v = base[i];
        s += v; sq += v * v;
    }
    ssum[threadIdx.x] = s; ssq[threadIdx.x] = sq;
    __syncthreads();
    for (int st = 512; st > 0; st >>= 1) {
        if (threadIdx.x < st) {
            ssum[threadIdx.x] += ssum[threadIdx.x + st];
            ssq[threadIdx.x]  += ssq[threadIdx.x + st];
        }
        __syncthreads();
    }
    if (threadIdx.x == 0) {
        float mean = ssum[0] * (1.f / (float)NPOS);
        float var  = ssq[0] * (1.f / (float)NPOS) - mean * mean;
        float inv  = rsqrtf(var + 1e-5f);
        float a = gamma[ch] * inv;
        g_scale[ch] = a;
        g_shift[ch] = beta[ch] - mean * a;
    }
}

__global__ void k_bnapply(float* __restrict__ out) {
    int idx = blockIdx.x * 256 + threadIdx.x;
    int ch = idx >> 15;
    float v = out[idx] * g_scale[ch] + g_shift[ch];
    out[idx] = fmaxf(v, 0.f);
}

extern "C" void kernel_launch(void* const* d_in, const int* in_sizes, int n_in,
                              void* d_out, int out_size) {
    const float* x     = (const float*)d_in[0];   // (1,64,16,16,16)
    const float* w_off = (const float*)d_in[1];   // (81,64,3,3,3)
    const float* b_off = (const float*)d_in[2];   // (81,)
    const float* w     = (const float*)d_in[3];   // (32,64,3,3,3)
    const float* b     = (const float*)d_in[4];   // (32,)
    const float* gamma = (const float*)d_in[5];   // (32,)
    const float* beta  = (const float*)d_in[6];   // (32,)
    float* out = (float*)d_out;                   // (1,32,32,32,32)

    k_wT<<<(27 * CIN * COUT + 255) / 256, 256>>>(w);
    k_weff<<<(8 * CIN * 8 * OPAD + 255) / 256, 256>>>(w_off);
    k_offconv<<<384, 128>>>(x, b_off);
    k_ygemm<<<256, 128>>>(x);
    k_scatter<<<4096, 256>>>(b, out);
    k_bnstat<<<COUT, 1024>>>(out, gamma, beta);
    k_bnapply<<<4096, 256>>>(out);
}